// round 11
// baseline (speedup 1.0000x reference)
#include <cuda_runtime.h>
#include <cstdint>

// WeightedBCELoss: out[b,s] = (labels[b,s]==0) ? -log(1-pred) : -weight[b]*log(pred)
// pred [4096,8192] f32, labels [4096,8192] i32, weight [4096] f32.
//
// R11 = R4 (certified best: ncu 53.2-54.7us, 82.9-84.9% DRAM) + L2::256B
// prefetch qualifier on the streaming loads (ld.global.cs.L2::256B.v4).
// Everything else identical: 16384 blocks x 256 thr, 2 float4/thread,
// MLP_p1=4 front-batched, uniform per-block weight, __stcs writes.

#define BATCH 4096
#define SENT  8192
#define V4_PER_ROW (SENT / 4)   // 2048
#define THREADS 256

__device__ __forceinline__ float4 ldcs_pf_f4(const float4* p) {
    float4 v;
    asm volatile("ld.global.cs.L2::256B.v4.f32 {%0,%1,%2,%3}, [%4];"
                 : "=f"(v.x), "=f"(v.y), "=f"(v.z), "=f"(v.w)
                 : "l"(p));
    return v;
}

__device__ __forceinline__ int4 ldcs_pf_i4(const int4* p) {
    int4 v;
    asm volatile("ld.global.cs.L2::256B.v4.u32 {%0,%1,%2,%3}, [%4];"
                 : "=r"(v.x), "=r"(v.y), "=r"(v.z), "=r"(v.w)
                 : "l"(p));
    return v;
}

__device__ __forceinline__ float bce_term(float p, int l, float w) {
    float a = (l == 0) ? (1.0f - p) : p;
    float s = (l == 0) ? 1.0f : w;
    return -s * __logf(a);
}

__global__ __launch_bounds__(THREADS, 8)
void wbce_kernel(const float4* __restrict__ pred,
                 const int4*   __restrict__ labels,
                 const float*  __restrict__ weight,
                 float4*       __restrict__ out)
{
    // Block covers float4 range [blk*512, blk*512+512) — entirely inside one
    // row (512 | 2048). row = blk >> 2. Weight is uniform per block.
    const int   row = blockIdx.x >> 2;
    const float w   = __ldg(&weight[row]);

    const long i0 = (long)blockIdx.x * 512 + threadIdx.x;
    const long i1 = i0 + 256;

    // Front-batched: 4 independent 16B loads (MLP_p1 = 4), with L2 prefetch.
    float4 p0 = ldcs_pf_f4(&pred[i0]);
    float4 p1 = ldcs_pf_f4(&pred[i1]);
    int4   l0 = ldcs_pf_i4(&labels[i0]);
    int4   l1 = ldcs_pf_i4(&labels[i1]);

    float4 o0, o1;
    o0.x = bce_term(p0.x, l0.x, w);
    o0.y = bce_term(p0.y, l0.y, w);
    o0.z = bce_term(p0.z, l0.z, w);
    o0.w = bce_term(p0.w, l0.w, w);
    o1.x = bce_term(p1.x, l1.x, w);
    o1.y = bce_term(p1.y, l1.y, w);
    o1.z = bce_term(p1.z, l1.z, w);
    o1.w = bce_term(p1.w, l1.w, w);

    __stcs(&out[i0], o0);
    __stcs(&out[i1], o1);
}

extern "C" void kernel_launch(void* const* d_in, const int* in_sizes, int n_in,
                              void* d_out, int out_size)
{
    const float4* pred   = (const float4*)d_in[0];
    const int4*   labels = (const int4*)d_in[1];
    const float*  weight = (const float*)d_in[2];
    float4*       out    = (float4*)d_out;

    const int total_v4 = BATCH * V4_PER_ROW;   // 8,388,608
    wbce_kernel<<<total_v4 / 512, THREADS>>>(pred, labels, weight, out);
}

// round 12
// speedup vs baseline: 1.0036x; 1.0036x over previous
#include <cuda_runtime.h>
#include <cstdint>

// WeightedBCELoss: out[b,s] = (labels[b,s]==0) ? -log(1-pred) : -weight[b]*log(pred)
// pred [4096,8192] f32, labels [4096,8192] i32, weight [4096] f32.
//
// R12 = R4 shape (16384 blocks x 256 thr, 2 float4/thread, MLP_p1=4
// front-batched, uniform per-block weight) with DEFAULT cache policy
// (plain loads/stores) — isolating the .cs variable, which was adopted
// in R2 together with a shape change and never tested alone at this shape.
// All other axes (MLP depth, grid/block shape, persistence, index width,
// L2 prefetch, write-through) already isolated and falsified/locked.

#define BATCH 4096
#define SENT  8192
#define V4_PER_ROW (SENT / 4)   // 2048
#define THREADS 256

__device__ __forceinline__ float bce_term(float p, int l, float w) {
    float a = (l == 0) ? (1.0f - p) : p;
    float s = (l == 0) ? 1.0f : w;
    return -s * __logf(a);
}

__global__ __launch_bounds__(THREADS, 8)
void wbce_kernel(const float4* __restrict__ pred,
                 const int4*   __restrict__ labels,
                 const float*  __restrict__ weight,
                 float4*       __restrict__ out)
{
    // Block covers float4 range [blk*512, blk*512+512) — entirely inside one
    // row (512 | 2048). row = blk >> 2. Weight is uniform per block.
    const int   row = blockIdx.x >> 2;
    const float w   = __ldg(&weight[row]);

    const long i0 = (long)blockIdx.x * 512 + threadIdx.x;
    const long i1 = i0 + 256;

    // Front-batched: 4 independent 16B loads (MLP_p1 = 4), default policy.
    float4 p0 = pred[i0];
    float4 p1 = pred[i1];
    int4   l0 = labels[i0];
    int4   l1 = labels[i1];

    float4 o0, o1;
    o0.x = bce_term(p0.x, l0.x, w);
    o0.y = bce_term(p0.y, l0.y, w);
    o0.z = bce_term(p0.z, l0.z, w);
    o0.w = bce_term(p0.w, l0.w, w);
    o1.x = bce_term(p1.x, l1.x, w);
    o1.y = bce_term(p1.y, l1.y, w);
    o1.z = bce_term(p1.z, l1.z, w);
    o1.w = bce_term(p1.w, l1.w, w);

    out[i0] = o0;
    out[i1] = o1;
}

extern "C" void kernel_launch(void* const* d_in, const int* in_sizes, int n_in,
                              void* d_out, int out_size)
{
    const float4* pred   = (const float4*)d_in[0];
    const int4*   labels = (const int4*)d_in[1];
    const float*  weight = (const float*)d_in[2];
    float4*       out    = (float4*)d_out;

    const int total_v4 = BATCH * V4_PER_ROW;   // 8,388,608
    wbce_kernel<<<total_v4 / 512, THREADS>>>(pred, labels, weight, out);
}

// round 13
// speedup vs baseline: 1.0041x; 1.0005x over previous
#include <cuda_runtime.h>
#include <cstdint>

// WeightedBCELoss: out[b,s] = (labels[b,s]==0) ? -log(1-pred) : -weight[b]*log(pred)
// pred [4096,8192] f32, labels [4096,8192] i32, weight [4096] f32.
//
// R13 = R12 shape (best measured: ncu 51.84us, 85.7% DRAM, 6786 GB/s) with the
// last untested policy cell: __ldcs loads (evict-first read lines free L2
// capacity for write buffering) + DEFAULT stores (lazy writeback won:
// stwt 81.2% < stcs 83-85% < default 85.7% — controller burst-forming).
// Shape: 16384 blocks x 256 thr, 2 float4/thread, MLP_p1=4 front-batched,
// uniform per-block weight broadcast, single __logf/element.

#define BATCH 4096
#define SENT  8192
#define V4_PER_ROW (SENT / 4)   // 2048
#define THREADS 256

__device__ __forceinline__ float bce_term(float p, int l, float w) {
    float a = (l == 0) ? (1.0f - p) : p;
    float s = (l == 0) ? 1.0f : w;
    return -s * __logf(a);
}

__global__ __launch_bounds__(THREADS, 8)
void wbce_kernel(const float4* __restrict__ pred,
                 const int4*   __restrict__ labels,
                 const float*  __restrict__ weight,
                 float4*       __restrict__ out)
{
    // Block covers float4 range [blk*512, blk*512+512) — entirely inside one
    // row (512 | 2048). row = blk >> 2. Weight is uniform per block.
    const int   row = blockIdx.x >> 2;
    const float w   = __ldg(&weight[row]);

    const long i0 = (long)blockIdx.x * 512 + threadIdx.x;
    const long i1 = i0 + 256;

    // Front-batched: 4 independent 16B loads (MLP_p1 = 4), evict-first reads.
    float4 p0 = __ldcs(&pred[i0]);
    float4 p1 = __ldcs(&pred[i1]);
    int4   l0 = __ldcs(&labels[i0]);
    int4   l1 = __ldcs(&labels[i1]);

    float4 o0, o1;
    o0.x = bce_term(p0.x, l0.x, w);
    o0.y = bce_term(p0.y, l0.y, w);
    o0.z = bce_term(p0.z, l0.z, w);
    o0.w = bce_term(p0.w, l0.w, w);
    o1.x = bce_term(p1.x, l1.x, w);
    o1.y = bce_term(p1.y, l1.y, w);
    o1.z = bce_term(p1.z, l1.z, w);
    o1.w = bce_term(p1.w, l1.w, w);

    // Default stores: lazy writeback -> large DRAM write bursts (measured best).
    out[i0] = o0;
    out[i1] = o1;
}

extern "C" void kernel_launch(void* const* d_in, const int* in_sizes, int n_in,
                              void* d_out, int out_size)
{
    const float4* pred   = (const float4*)d_in[0];
    const int4*   labels = (const int4*)d_in[1];
    const float*  weight = (const float*)d_in[2];
    float4*       out    = (float4*)d_out;

    const int total_v4 = BATCH * V4_PER_ROW;   // 8,388,608
    wbce_kernel<<<total_v4 / 512, THREADS>>>(pred, labels, weight, out);
}